// round 16
// baseline (speedup 1.0000x reference)
#include <cuda_runtime.h>
#include <cstdint>

#define S_LEN 16384
#define D_DIM 256
#define V_DIM 8
#define K_HEADS 24
#define NBUCKET 1024
#define ROW_F 260
#define ROWS_TILE 16
#define T_ITER 8
#define WARPS_CTA 2
#define ROWS_CTA (WARPS_CTA * ROWS_TILE * T_ITER)   // 256 records per CTA
#define TILE_B (ROWS_TILE * ROW_F * 4)
#define MBAR_PAD 128
#define SMEM_BYTES (MBAR_PAD + WARPS_CTA * 2 * TILE_B)

// Sort scratch (static __device__ allocations are allowed)
__device__ unsigned int g_sorted[K_HEADS * S_LEN];
__device__ int g_base[K_HEADS][NBUCKET];
__device__ int g_cursor[K_HEADS][NBUCKET];

// ---- Prep 1: per-head histogram (one CTA per head, smem-accumulated).
__global__ void hist_kernel(const int* __restrict__ mask_idx) {
    __shared__ int h[NBUCKET];
    const int k = blockIdx.x;
    for (int b = threadIdx.x; b < NBUCKET; b += blockDim.x) h[b] = 0;
    __syncthreads();
    for (int s = threadIdx.x; s < S_LEN; s += blockDim.x)
        atomicAdd(&h[mask_idx[k * S_LEN + s] >> 7], 1);
    __syncthreads();
    for (int b = threadIdx.x; b < NBUCKET; b += blockDim.x)
        g_base[k][b] = h[b];
}

// ---- Prep 2: exclusive scan per head (1024 threads, Hillis-Steele).
__global__ void scan_kernel() {
    __shared__ int sh[NBUCKET];
    const int k = blockIdx.x, t = threadIdx.x;
    const int v = g_base[k][t];
    sh[t] = v;
    __syncthreads();
    #pragma unroll
    for (int off = 1; off < NBUCKET; off <<= 1) {
        int add = (t >= off) ? sh[t - off] : 0;
        __syncthreads();
        sh[t] += add;
        __syncthreads();
    }
    g_cursor[k][t] = sh[t] - v;
}

// ---- Prep 3: scatter records (s:14b << 17 | idx:17b) into bucket order.
__global__ void scatter_kernel(const int* __restrict__ mask_idx) {
    const int k = blockIdx.x;
    for (int s = threadIdx.x; s < S_LEN; s += blockDim.x) {
        int idx = mask_idx[k * S_LEN + s];
        int pos = atomicAdd(&g_cursor[k][idx >> 7], 1);
        g_sorted[k * S_LEN + pos] = ((unsigned)s << 17) | (unsigned)idx;
    }
}

__device__ __forceinline__ uint32_t f2tf32(float f) {
    uint32_t u;
    asm("cvt.rna.tf32.f32 %0, %1;" : "=r"(u) : "f"(f));
    return u;
}

// ---- Main: R15 double-buffered TMA + HMMA engine on the sorted stream.
__global__ __launch_bounds__(64, 3)
void attr_decoder_hmma(const float* __restrict__ feats,      // [N, 256]
                       const float* __restrict__ Wh,         // [24, 256, 8]
                       const float* __restrict__ bias,       // [24, 8]
                       float*       __restrict__ out)        // [24, 16384, 8]
{
    extern __shared__ __align__(16) char smem[];
    const int k    = blockIdx.x;               // head FAST -> concurrent CTAs
    const int lane = threadIdx.x & 31;         //  share one table window
    const int warp = threadIdx.x >> 5;
    const int sct  = blockIdx.y * ROWS_CTA;    // position in sorted stream

    const int tg  = lane & 3;
    const int gid = lane >> 2;

    const uint32_t sbase = (uint32_t)__cvta_generic_to_shared(smem);
    const uint32_t mbar0 = sbase + warp * 32;
    float* bufp[2] = {
        (float*)(smem + MBAR_PAD + (warp * 2 + 0) * TILE_B),
        (float*)(smem + MBAR_PAD + (warp * 2 + 1) * TILE_B)};
    const uint32_t bufs[2] = {
        (uint32_t)__cvta_generic_to_shared(bufp[0]),
        (uint32_t)__cvta_generic_to_shared(bufp[1])};

    if (lane == 0) {
        asm volatile("mbarrier.init.shared.b64 [%0], 1;" :: "r"(mbar0) : "memory");
        asm volatile("mbarrier.init.shared.b64 [%0], 1;" :: "r"(mbar0 + 16) : "memory");
    }
    __syncwarp();

    // Preload this warp's 128 sorted records (lane&15 holds tile r's row).
    unsigned myrec[T_ITER];
    #pragma unroll
    for (int r = 0; r < T_ITER; ++r)
        myrec[r] = g_sorted[(size_t)k * S_LEN + sct + r * (WARPS_CTA * ROWS_TILE)
                            + warp * ROWS_TILE + (lane & 15)];

    auto issue = [&](int r, int b) {
        if (lane == 0)
            asm volatile("mbarrier.arrive.expect_tx.shared.b64 _, [%0], %1;"
                         :: "r"(mbar0 + b * 16), "r"(ROWS_TILE * 1024u) : "memory");
        __syncwarp();
        if (lane < ROWS_TILE) {
            const float* src = feats + (size_t)(myrec[r] & 0x1FFFF) * D_DIM;
            asm volatile(
                "cp.async.bulk.shared::cta.global.mbarrier::complete_tx::bytes "
                "[%0], [%1], %2, [%3];"
                :: "r"(bufs[b] + lane * (ROW_F * 4)), "l"(src), "r"(1024u),
                   "r"(mbar0 + b * 16) : "memory");
        }
    };

    issue(0, 0);

    // B fragments (weights), loaded once while the first TMA flies.
    const float* wb = Wh + (size_t)k * (D_DIM * V_DIM);
    uint32_t b0[32], b1[32];
    #pragma unroll
    for (int kk = 0; kk < 32; ++kk) {
        b0[kk] = f2tf32(wb[(kk * 8 + tg    ) * V_DIM + gid]);
        b1[kk] = f2tf32(wb[(kk * 8 + tg + 4) * V_DIM + gid]);
    }
    const float bv0 = bias[k * V_DIM + 2 * tg];
    const float bv1 = bias[k * V_DIM + 2 * tg + 1];

    #pragma unroll
    for (int r = 0; r < T_ITER; ++r) {
        const int b = r & 1;
        const uint32_t mb = mbar0 + b * 16;
        const uint32_t ph = (r >> 1) & 1;
        {
            uint32_t done;
            asm volatile(
                "{\n\t.reg .pred p;\n\t"
                "mbarrier.try_wait.parity.acquire.cta.shared::cta.b64 p, [%1], %2;\n\t"
                "selp.b32 %0, 1, 0, p;\n\t}"
                : "=r"(done) : "r"(mb), "r"(ph) : "memory");
            if (!done) {
                asm volatile(
                    "{\n\t.reg .pred P;\n\t"
                    "W%=:\n\t"
                    "mbarrier.try_wait.parity.acquire.cta.shared::cta.b64 P, [%0], %1, 0x989680;\n\t"
                    "@P bra D%=;\n\tbra W%=;\n\tD%=:\n\t}"
                    :: "r"(mb), "r"(ph) : "memory");
            }
        }

        if (r + 1 < T_ITER) issue(r + 1, b ^ 1);

        // 32 x mma.sync m16n8k8 tf32; stride-260 pad -> conflict-free LDS.
        const float* arow = bufp[b] + gid * ROW_F + tg;
        float e0 = 0.f, e1 = 0.f, e2 = 0.f, e3 = 0.f;
        float q0 = 0.f, q1 = 0.f, q2 = 0.f, q3 = 0.f;
        #pragma unroll
        for (int kk = 0; kk < 32; ++kk) {
            const float* p = arow + kk * 8;
            uint32_t a0 = f2tf32(p[0]);
            uint32_t a2 = f2tf32(p[4]);
            uint32_t a1 = f2tf32(p[8 * ROW_F]);
            uint32_t a3 = f2tf32(p[8 * ROW_F + 4]);
            if (kk & 1) {
                asm("mma.sync.aligned.m16n8k8.row.col.f32.tf32.tf32.f32 "
                    "{%0,%1,%2,%3}, {%4,%5,%6,%7}, {%8,%9}, {%0,%1,%2,%3};"
                    : "+f"(q0), "+f"(q1), "+f"(q2), "+f"(q3)
                    : "r"(a0), "r"(a1), "r"(a2), "r"(a3), "r"(b0[kk]), "r"(b1[kk]));
            } else {
                asm("mma.sync.aligned.m16n8k8.row.col.f32.tf32.tf32.f32 "
                    "{%0,%1,%2,%3}, {%4,%5,%6,%7}, {%8,%9}, {%0,%1,%2,%3};"
                    : "+f"(e0), "+f"(e1), "+f"(e2), "+f"(e3)
                    : "r"(a0), "r"(a1), "r"(a2), "r"(a3), "r"(b0[kk]), "r"(b1[kk]));
            }
        }

        // Scattered stores: rows go to their ORIGINAL s (record >> 17).
        const int s_lo = __shfl_sync(0xffffffffu, myrec[r], gid) >> 17;
        const int s_hi = __shfl_sync(0xffffffffu, myrec[r], gid + 8) >> 17;
        const float d0 = e0 + q0 + bv0;
        const float d1 = e1 + q1 + bv1;
        const float d2 = e2 + q2 + bv0;
        const float d3 = e3 + q3 + bv1;
        float2* o_lo = (float2*)(out + ((size_t)k * S_LEN + s_lo) * V_DIM + 2 * tg);
        float2* o_hi = (float2*)(out + ((size_t)k * S_LEN + s_hi) * V_DIM + 2 * tg);
        *o_lo = make_float2(d0, d1);
        *o_hi = make_float2(d2, d3);
    }
}

extern "C" void kernel_launch(void* const* d_in, const int* in_sizes, int n_in,
                              void* d_out, int out_size) {
    // metadata order: block_type_grid (unused), features, mask_idx, head_weights, head_bias
    const float* feats    = (const float*)d_in[1];
    const int*   mask_idx = (const int*)  d_in[2];
    const float* Wh       = (const float*)d_in[3];
    const float* bias     = (const float*)d_in[4];
    float*       out      = (float*)d_out;

    hist_kernel<<<K_HEADS, 256>>>(mask_idx);
    scan_kernel<<<K_HEADS, NBUCKET>>>();
    scatter_kernel<<<K_HEADS, 256>>>(mask_idx);

    cudaFuncSetAttribute(attr_decoder_hmma,
                         cudaFuncAttributeMaxDynamicSharedMemorySize, SMEM_BYTES);
    dim3 grid(K_HEADS, S_LEN / ROWS_CTA);   // head FAST, stream-chunk slow
    attr_decoder_hmma<<<grid, 64, SMEM_BYTES>>>(feats, Wh, bias, out);
}

// round 17
// speedup vs baseline: 1.6021x; 1.6021x over previous
#include <cuda_runtime.h>
#include <cstdint>

#define S_LEN 16384
#define D_DIM 256
#define V_DIM 8
#define K_HEADS 24
#define ROW_F 260                              // padded smem row stride (1040 B)
#define ROWS_TILE 16
#define T_ITER 8                               // tiles per warp
#define NBUF 3                                 // triple buffer: 2 tiles in flight
#define WARPS_CTA 2
#define ROWS_CTA (WARPS_CTA * ROWS_TILE * T_ITER)   // 256 rows per CTA
#define TILE_B (ROWS_TILE * ROW_F * 4)         // 16640 B
#define MBAR_PAD 128
#define SMEM_BYTES (MBAR_PAD + WARPS_CTA * NBUF * TILE_B)   // 128 + 99840

__device__ __forceinline__ uint32_t f2tf32(float f) {
    uint32_t u;
    asm("cvt.rna.tf32.f32 %0, %1;" : "=r"(u) : "f"(f));
    return u;
}

__global__ __launch_bounds__(64)
void attr_decoder_hmma(const float* __restrict__ feats,      // [N, 256]
                       const int*   __restrict__ mask_idx,   // [24, 16384]
                       const float* __restrict__ Wh,         // [24, 256, 8]
                       const float* __restrict__ bias,       // [24, 8]
                       float*       __restrict__ out)        // [24, 16384, 8]
{
    extern __shared__ __align__(16) char smem[];
    const int k    = blockIdx.y;
    const int lane = threadIdx.x & 31;
    const int warp = threadIdx.x >> 5;         // 0..1
    const int sct  = blockIdx.x * ROWS_CTA;

    const int tg  = lane & 3;                  // k-col / out-col pair
    const int gid = lane >> 2;                 // row in half-tile / v for B

    const uint32_t sbase = (uint32_t)__cvta_generic_to_shared(smem);
    const uint32_t mbar0 = sbase + warp * (NBUF * 16);   // 3 mbars per warp
    float* bufp[NBUF];
    uint32_t bufs[NBUF];
    #pragma unroll
    for (int b = 0; b < NBUF; ++b) {
        bufp[b] = (float*)(smem + MBAR_PAD + (warp * NBUF + b) * TILE_B);
        bufs[b] = (uint32_t)__cvta_generic_to_shared(bufp[b]);
    }

    // ---- 1. Warp-private mbarriers (one per buffer).
    if (lane == 0) {
        #pragma unroll
        for (int b = 0; b < NBUF; ++b)
            asm volatile("mbarrier.init.shared.b64 [%0], 1;"
                         :: "r"(mbar0 + b * 16) : "memory");
    }
    __syncwarp();

    // ---- 2. Preload this warp's 128 gather indices (lane&15 = tile r's row).
    int myidx[T_ITER];
    #pragma unroll
    for (int r = 0; r < T_ITER; ++r)
        myidx[r] = mask_idx[(size_t)k * S_LEN + sct + r * (WARPS_CTA * ROWS_TILE)
                            + warp * ROWS_TILE + (lane & 15)];

    // Bulk-gather one 16-row tile into buffer b.
    auto issue = [&](int r, int b) {
        if (lane == 0)
            asm volatile("mbarrier.arrive.expect_tx.shared.b64 _, [%0], %1;"
                         :: "r"(mbar0 + b * 16), "r"(ROWS_TILE * 1024u) : "memory");
        __syncwarp();
        if (lane < ROWS_TILE) {
            const float* src = feats + (size_t)myidx[r] * D_DIM;
            asm volatile(
                "cp.async.bulk.shared::cta.global.mbarrier::complete_tx::bytes "
                "[%0], [%1], %2, [%3];"
                :: "r"(bufs[b] + lane * (ROW_F * 4)), "l"(src), "r"(1024u),
                   "r"(mbar0 + b * 16) : "memory");
        }
    };

    // ---- 3. Prologue: TWO tiles in flight, then amortized B-fragment load.
    issue(0, 0);
    issue(1, 1);

    const float* wb = Wh + (size_t)k * (D_DIM * V_DIM);
    uint32_t b0[32], b1[32];
    #pragma unroll
    for (int kk = 0; kk < 32; ++kk) {
        b0[kk] = f2tf32(wb[(kk * 8 + tg    ) * V_DIM + gid]);
        b1[kk] = f2tf32(wb[(kk * 8 + tg + 4) * V_DIM + gid]);
    }
    const float bv0 = bias[k * V_DIM + 2 * tg];
    const float bv1 = bias[k * V_DIM + 2 * tg + 1];

    // ---- 4. Pipelined loop: wait(r) -> issue(r+2) -> MMA(r) -> store(r).
    #pragma unroll
    for (int r = 0; r < T_ITER; ++r) {
        const int b = r % NBUF;
        const uint32_t mb = mbar0 + b * 16;
        const uint32_t ph = (r / NBUF) & 1;    // buffer b's use-count parity
        {
            uint32_t done;
            asm volatile(
                "{\n\t.reg .pred p;\n\t"
                "mbarrier.try_wait.parity.acquire.cta.shared::cta.b64 p, [%1], %2;\n\t"
                "selp.b32 %0, 1, 0, p;\n\t}"
                : "=r"(done) : "r"(mb), "r"(ph) : "memory");
            if (!done) {
                asm volatile(
                    "{\n\t.reg .pred P;\n\t"
                    "W%=:\n\t"
                    "mbarrier.try_wait.parity.acquire.cta.shared::cta.b64 P, [%0], %1, 0x989680;\n\t"
                    "@P bra D%=;\n\tbra W%=;\n\tD%=:\n\t}"
                    :: "r"(mb), "r"(ph) : "memory");
            }
        }

        // Keep 2 tiles in flight: next goes into the buffer computed at r-1.
        if (r + 2 < T_ITER) issue(r + 2, (r + 2) % NBUF);

        // 32 x mma.sync m16n8k8 tf32; stride-260 pad -> conflict-free LDS.
        const float* arow = bufp[b] + gid * ROW_F + tg;
        float e0 = 0.f, e1 = 0.f, e2 = 0.f, e3 = 0.f;
        float q0 = 0.f, q1 = 0.f, q2 = 0.f, q3 = 0.f;
        #pragma unroll
        for (int kk = 0; kk < 32; ++kk) {
            const float* p = arow + kk * 8;
            uint32_t a0 = f2tf32(p[0]);
            uint32_t a2 = f2tf32(p[4]);
            uint32_t a1 = f2tf32(p[8 * ROW_F]);
            uint32_t a3 = f2tf32(p[8 * ROW_F + 4]);
            if (kk & 1) {
                asm("mma.sync.aligned.m16n8k8.row.col.f32.tf32.tf32.f32 "
                    "{%0,%1,%2,%3}, {%4,%5,%6,%7}, {%8,%9}, {%0,%1,%2,%3};"
                    : "+f"(q0), "+f"(q1), "+f"(q2), "+f"(q3)
                    : "r"(a0), "r"(a1), "r"(a2), "r"(a3), "r"(b0[kk]), "r"(b1[kk]));
            } else {
                asm("mma.sync.aligned.m16n8k8.row.col.f32.tf32.tf32.f32 "
                    "{%0,%1,%2,%3}, {%4,%5,%6,%7}, {%8,%9}, {%0,%1,%2,%3};"
                    : "+f"(e0), "+f"(e1), "+f"(e2), "+f"(e3)
                    : "r"(a0), "r"(a1), "r"(a2), "r"(a3), "r"(b0[kk]), "r"(b1[kk]));
            }
        }

        const int s0 = sct + r * (WARPS_CTA * ROWS_TILE) + warp * ROWS_TILE;
        const float d0 = e0 + q0 + bv0;
        const float d1 = e1 + q1 + bv1;
        const float d2 = e2 + q2 + bv0;
        const float d3 = e3 + q3 + bv1;
        float2* o_lo = (float2*)(out + ((size_t)k * S_LEN + s0 + gid) * V_DIM + 2 * tg);
        float2* o_hi = (float2*)(out + ((size_t)k * S_LEN + s0 + gid + 8) * V_DIM + 2 * tg);
        *o_lo = make_float2(d0, d1);
        *o_hi = make_float2(d2, d3);
    }
}

extern "C" void kernel_launch(void* const* d_in, const int* in_sizes, int n_in,
                              void* d_out, int out_size) {
    // metadata order: block_type_grid (unused), features, mask_idx, head_weights, head_bias
    const float* feats    = (const float*)d_in[1];
    const int*   mask_idx = (const int*)  d_in[2];
    const float* Wh       = (const float*)d_in[3];
    const float* bias     = (const float*)d_in[4];
    float*       out      = (float*)d_out;

    cudaFuncSetAttribute(attr_decoder_hmma,
                         cudaFuncAttributeMaxDynamicSharedMemorySize, SMEM_BYTES);
    dim3 grid(S_LEN / ROWS_CTA, K_HEADS);   // 64 x 24 CTAs, 256 rows each
    attr_decoder_hmma<<<grid, 64, SMEM_BYTES>>>(feats, mask_idx, Wh, bias, out);
}